// round 1
// baseline (speedup 1.0000x reference)
#include <cuda_runtime.h>

// WaveletNet: 4 lifting steps with length-1 filters == elementwise 2x2 linear map.
// out[b, 0:L2]   = m00*x[b,2i] + m01*x[b,2i+1]   (evens/average)
// out[b, L2:2L2] = m10*x[b,2i] + m11*x[b,2i+1]   (odds/detail)
// where M = prod_{k=3..0} [[1-u_k p_k, u_k], [-p_k, 1]]
// Plus trailing log_det = 0 if out_size > B*L.

#define L_FULL 65536
#define L_HALF 32768
#define B_DIM  256
#define QUADS_PER_ROW (L_FULL / 4)        // 16384
#define QUAD_SHIFT 14
#define QUAD_MASK  (QUADS_PER_ROW - 1)
#define N_QUADS ((long long)B_DIM * QUADS_PER_ROW)  // 4,194,304
#define Z_ELEMS ((long long)B_DIM * L_FULL)         // 16,777,216

__global__ void __launch_bounds__(256)
wavelet_fused_kernel(const float4* __restrict__ x4,
                     const float* __restrict__ P,
                     const float* __restrict__ U,
                     float* __restrict__ out,
                     long long out_size)
{
    // Compose the 4 lifting steps into one 2x2 matrix (cheap, coeffs L1-cached).
    float m00 = 1.f, m01 = 0.f, m10 = 0.f, m11 = 1.f;
#pragma unroll
    for (int k = 0; k < 4; k++) {
        float p = __ldg(&P[k]);
        float u = __ldg(&U[k]);
        // M_k = [[1-u*p, u], [-p, 1]]
        float a00 = 1.f - u * p, a01 = u;
        float a10 = -p,          a11 = 1.f;
        float n00 = a00 * m00 + a01 * m10;
        float n01 = a00 * m01 + a01 * m11;
        float n10 = a10 * m00 + a11 * m10;
        float n11 = a10 * m01 + a11 * m11;
        m00 = n00; m01 = n01; m10 = n10; m11 = n11;
    }

    long long g = (long long)blockIdx.x * blockDim.x + threadIdx.x;
    if (g < N_QUADS) {
        long long b = g >> QUAD_SHIFT;
        long long q = g & QUAD_MASK;

        float4 v = x4[g];   // (e0, o0, e1, o1): two consecutive (even, odd) pairs

        float2 ev, od;
        ev.x = m00 * v.x + m01 * v.y;
        od.x = m10 * v.x + m11 * v.y;
        ev.y = m00 * v.z + m01 * v.w;
        od.y = m10 * v.z + m11 * v.w;

        float* row = out + b * (long long)L_FULL;
        long long i = 2 * q;                         // pair index within row (8B aligned)
        *reinterpret_cast<float2*>(row + i)          = ev;  // evens half
        *reinterpret_cast<float2*>(row + L_HALF + i) = od;  // details half
    }

    // log_det (and any padding beyond z) = 0
    if (g == 0) {
        for (long long i = Z_ELEMS; i < out_size; i++) out[i] = 0.0f;
    }
}

extern "C" void kernel_launch(void* const* d_in, const int* in_sizes, int n_in,
                              void* d_out, int out_size)
{
    const float4* x4 = (const float4*)d_in[0];
    const float*  P  = (const float*)d_in[1];
    const float*  U  = (const float*)d_in[2];
    float* out = (float*)d_out;

    const int threads = 256;
    const int blocks = (int)((N_QUADS + threads - 1) / threads);  // 16384
    wavelet_fused_kernel<<<blocks, threads>>>(x4, P, U, out, (long long)out_size);
}

// round 2
// speedup vs baseline: 1.2618x; 1.2618x over previous
#include <cuda_runtime.h>

// WaveletNet: 4 lifting steps with length-1 filters == elementwise 2x2 linear map.
// Evens half of each output row: m00*e + m01*o ; details half: m10*e + m11*o,
// with M = prod_{k=3..0} [[1-u_k p_k, u_k], [-p_k, 1]].
// R2: 2x float4 load per thread (MLP=2), float4 stores, streaming cache hints.

#define L_FULL 65536
#define L_HALF 32768
#define B_DIM  256
#define OCTS_PER_ROW (L_FULL / 8)          // 8192 (one oct = 8 floats = 4 pairs)
#define OCT_SHIFT 13
#define OCT_MASK  (OCTS_PER_ROW - 1)
#define N_OCTS ((long long)B_DIM * OCTS_PER_ROW)   // 2,097,152
#define Z_ELEMS ((long long)B_DIM * L_FULL)        // 16,777,216

__global__ void __launch_bounds__(256)
wavelet_fused_kernel(const float4* __restrict__ x4,
                     const float* __restrict__ P,
                     const float* __restrict__ U,
                     float* __restrict__ out,
                     long long out_size)
{
    // Compose the 4 lifting steps into one 2x2 matrix (coeffs L1-cached, cheap).
    float m00 = 1.f, m01 = 0.f, m10 = 0.f, m11 = 1.f;
#pragma unroll
    for (int k = 0; k < 4; k++) {
        float p = __ldg(&P[k]);
        float u = __ldg(&U[k]);
        float a00 = 1.f - u * p, a01 = u;
        float a10 = -p,          a11 = 1.f;
        float n00 = a00 * m00 + a01 * m10;
        float n01 = a00 * m01 + a01 * m11;
        float n10 = a10 * m00 + a11 * m10;
        float n11 = a10 * m01 + a11 * m11;
        m00 = n00; m01 = n01; m10 = n10; m11 = n11;
    }

    long long g = (long long)blockIdx.x * blockDim.x + threadIdx.x;
    if (g < N_OCTS) {
        long long b = g >> OCT_SHIFT;
        long long q = g & OCT_MASK;

        // Two independent 16B loads, issued back-to-back (MLP=2), streaming.
        const float4* src = x4 + 2 * g;
        float4 v0 = __ldcs(src);
        float4 v1 = __ldcs(src + 1);

        float4 ev, od;
        ev.x = m00 * v0.x + m01 * v0.y;
        od.x = m10 * v0.x + m11 * v0.y;
        ev.y = m00 * v0.z + m01 * v0.w;
        od.y = m10 * v0.z + m11 * v0.w;
        ev.z = m00 * v1.x + m01 * v1.y;
        od.z = m10 * v1.x + m11 * v1.y;
        ev.w = m00 * v1.z + m01 * v1.w;
        od.w = m10 * v1.z + m11 * v1.w;

        float* row = out + b * (long long)L_FULL;
        long long i = 4 * q;  // 4 pairs per oct -> 4 floats per half-row (16B aligned)
        __stcs(reinterpret_cast<float4*>(row + i), ev);           // evens half
        __stcs(reinterpret_cast<float4*>(row + L_HALF + i), od);  // details half
    }

    // log_det (and any padding beyond z) = 0
    if (g == 0) {
        for (long long i = Z_ELEMS; i < out_size; i++) out[i] = 0.0f;
    }
}

extern "C" void kernel_launch(void* const* d_in, const int* in_sizes, int n_in,
                              void* d_out, int out_size)
{
    const float4* x4 = (const float4*)d_in[0];
    const float*  P  = (const float*)d_in[1];
    const float*  U  = (const float*)d_in[2];
    float* out = (float*)d_out;

    const int threads = 256;
    const int blocks = (int)((N_OCTS + threads - 1) / threads);  // 8192
    wavelet_fused_kernel<<<blocks, threads>>>(x4, P, U, out, (long long)out_size);
}